// round 16
// baseline (speedup 1.0000x reference)
#include <cuda_runtime.h>
#include <math.h>
#include <stdint.h>

// Problem constants
#define B_    2
#define L_    2048
#define DM    1024
#define DI    2048
#define DS    16
#define DR    64
#define XD    96            // DR + 2*DS
#define MTOK  (B_ * L_)     // 4096 tokens

// Scratch (device globals: allocation-free)
__device__ float g_xz[(size_t)MTOK * (2 * DI)];
__device__ float g_xc[(size_t)MTOK * DI];
__device__ float g_xdbl[(size_t)MTOK * XD];
__device__ float g_delta[(size_t)MTOK * DI];
__device__ float g_g[(size_t)MTOK * DI];
// Pre-rounded (tf32) copies
__device__ float g_rx [(size_t)MTOK * DM];        // x
__device__ float g_rw1[(size_t)(2 * DI) * DM];    // in_proj_w
__device__ float g_rw3[(size_t)XD * DI];          // x_proj_w
__device__ float g_rw4[(size_t)DI * DR];          // dt_proj_w
__device__ float g_rw6[(size_t)DM * DI];          // out_proj_w

// ---------------------------------------------------------------------------
// TF32 helpers
// ---------------------------------------------------------------------------
__device__ __forceinline__ unsigned f2tf32(float f) {
    unsigned r;
    asm("cvt.rna.tf32.f32 %0, %1;" : "=r"(r) : "f"(f));
    return r;
}
__device__ __forceinline__ float tf32r(float f) {
    return __uint_as_float(f2tf32(f));
}

__device__ __forceinline__ void mma_tf32(float (&d)[4], const unsigned (&a)[4],
                                         const unsigned (&b)[2]) {
    asm volatile(
        "mma.sync.aligned.m16n8k8.row.col.f32.tf32.tf32.f32 "
        "{%0,%1,%2,%3}, {%4,%5,%6,%7}, {%8,%9}, {%0,%1,%2,%3};\n"
        : "+f"(d[0]), "+f"(d[1]), "+f"(d[2]), "+f"(d[3])
        : "r"(a[0]), "r"(a[1]), "r"(a[2]), "r"(a[3]),
          "r"(b[0]), "r"(b[1]));
}

// ---------------------------------------------------------------------------
// Pre-round: dst = round_tf32(src), float4 elementwise.
// ---------------------------------------------------------------------------
__global__ void round_tf32_kernel(const float* __restrict__ src,
                                  float* __restrict__ dst, int n4)
{
    int i = blockIdx.x * blockDim.x + threadIdx.x;
    if (i >= n4) return;
    float4 v = ((const float4*)src)[i];
    v.x = tf32r(v.x); v.y = tf32r(v.y); v.z = tf32r(v.z); v.w = tf32r(v.w);
    ((float4*)dst)[i] = v;
}

// ---------------------------------------------------------------------------
// SIMT TF32 MMA GEMM (R10-measured layout). C[M,N] = A[M,K] @ B[N,K]^T.
// Double-buffered smem, register-staged prefetch, one sync per tile.
// B operand must be pre-rounded to tf32. A is rounded in-kernel iff CVTA=1
// (use CVTA=0 when A is already tf32-rounded in gmem).
// EPI=0: plain store. EPI=1: +=bias, softplus.
// ---------------------------------------------------------------------------
template <int BM, int BN, int BK, int WRM, int WRN, int EPI, int CVTA>
__global__ void __launch_bounds__(256) mma_gemm_nt(
    const float* __restrict__ A, const float* __restrict__ Bw,
    float* __restrict__ C, int M, int N, int K,
    int lda, int ldb, int ldc, const float* __restrict__ bias)
{
    constexpr int WM = BM / WRM, WN = BN / WRN;
    constexpr int MI = WM / 16, NI = WN / 8;
    constexpr int LDSZ = BK + 4;
    constexpr int K4 = BK / 4;
    constexpr int AF4 = BM * K4;
    constexpr int BF4 = BN * K4;
    constexpr int AP = (AF4 + 255) / 256;
    constexpr int BP = (BF4 + 255) / 256;

    __shared__ float As[2][BM][LDSZ];
    __shared__ float Bs[2][BN][LDSZ];

    const int tid  = threadIdx.x;
    const int lane = tid & 31;
    const int warp = tid >> 5;
    const int wm = (warp % WRM) * WM;
    const int wn = (warp / WRM) * WN;
    const int m0 = blockIdx.y * BM;
    const int n0 = blockIdx.x * BN;
    const int g  = lane >> 2;
    const int tg = lane & 3;

    float4 ar[AP], br[BP];

    auto load_ab = [&](int k0) {
#pragma unroll
        for (int p = 0; p < AP; p++) {
            int i = tid + p * 256;
            if ((AF4 % 256 == 0) || i < AF4)
                ar[p] = *(const float4*)&A[(size_t)(m0 + i / K4) * lda + k0 + (i % K4) * 4];
        }
#pragma unroll
        for (int p = 0; p < BP; p++) {
            int i = tid + p * 256;
            if ((BF4 % 256 == 0) || i < BF4)
                br[p] = *(const float4*)&Bw[(size_t)(n0 + i / K4) * ldb + k0 + (i % K4) * 4];
        }
    };
    auto store_ab = [&](int s) {
#pragma unroll
        for (int p = 0; p < AP; p++) {
            int i = tid + p * 256;
            if ((AF4 % 256 == 0) || i < AF4) {
                float4 v = ar[p];
                if (CVTA) {
                    v.x = tf32r(v.x); v.y = tf32r(v.y);
                    v.z = tf32r(v.z); v.w = tf32r(v.w);
                }
                *(float4*)&As[s][i / K4][(i % K4) * 4] = v;
            }
        }
#pragma unroll
        for (int p = 0; p < BP; p++) {
            int i = tid + p * 256;
            if ((BF4 % 256 == 0) || i < BF4)
                *(float4*)&Bs[s][i / K4][(i % K4) * 4] = br[p];
        }
    };

    float acc[MI][NI][4];
#pragma unroll
    for (int mi = 0; mi < MI; mi++)
#pragma unroll
        for (int ni = 0; ni < NI; ni++)
#pragma unroll
            for (int j = 0; j < 4; j++) acc[mi][ni][j] = 0.f;

    load_ab(0);
    store_ab(0);
    __syncthreads();

    const int nt = K / BK;
#pragma unroll 1
    for (int t = 0; t < nt; t++) {
        const int s = t & 1;
        if (t + 1 < nt) load_ab((t + 1) * BK);

#pragma unroll
        for (int kk = 0; kk < BK; kk += 8) {
            unsigned af[MI][4], bf[NI][2];
#pragma unroll
            for (int mi = 0; mi < MI; mi++) {
                const int r = wm + mi * 16;
                af[mi][0] = __float_as_uint(As[s][r + g][kk + tg]);
                af[mi][1] = __float_as_uint(As[s][r + 8 + g][kk + tg]);
                af[mi][2] = __float_as_uint(As[s][r + g][kk + 4 + tg]);
                af[mi][3] = __float_as_uint(As[s][r + 8 + g][kk + 4 + tg]);
            }
#pragma unroll
            for (int ni = 0; ni < NI; ni++) {
                const int cn = wn + ni * 8 + g;
                bf[ni][0] = __float_as_uint(Bs[s][cn][kk + tg]);
                bf[ni][1] = __float_as_uint(Bs[s][cn][kk + 4 + tg]);
            }
#pragma unroll
            for (int mi = 0; mi < MI; mi++)
#pragma unroll
                for (int ni = 0; ni < NI; ni++)
                    mma_tf32(acc[mi][ni], af[mi], bf[ni]);
        }

        if (t + 1 < nt) store_ab(s ^ 1);
        __syncthreads();
    }

#pragma unroll
    for (int mi = 0; mi < MI; mi++) {
#pragma unroll
        for (int ni = 0; ni < NI; ni++) {
#pragma unroll
            for (int half = 0; half < 2; half++) {
                int row = m0 + wm + mi * 16 + g + half * 8;
                int col = n0 + wn + ni * 8 + tg * 2;
                float v0 = acc[mi][ni][half * 2 + 0];
                float v1 = acc[mi][ni][half * 2 + 1];
                if (EPI == 1) {
                    v0 += bias[col];
                    v1 += bias[col + 1];
                    v0 = (v0 > 20.f) ? v0 : log1pf(expf(v0));
                    v1 = (v1 > 20.f) ? v1 : log1pf(expf(v1));
                }
                *(float2*)&C[(size_t)row * ldc + col] = make_float2(v0, v1);
            }
        }
    }
}

// ---------------------------------------------------------------------------
// Causal depthwise conv1d (W=4) + bias + SiLU, vectorized over 4 channels.
// Output NOT rounded (scan consumes it raw; GEMM3 rounds via CVTA).
// ---------------------------------------------------------------------------
__global__ void conv_silu_kernel(const float* __restrict__ xz,
                                 const float* __restrict__ cw,
                                 const float* __restrict__ cb,
                                 float* __restrict__ xc)
{
    int idx = blockIdx.x * blockDim.x + threadIdx.x;
    if (idx >= MTOK * DI / 4) return;
    int c4 = idx % (DI / 4);
    int t  = idx / (DI / 4);
    int l  = t % L_;
    int c  = c4 * 4;

    float4 w0 = *(const float4*)&cw[(c + 0) * 4];
    float4 w1 = *(const float4*)&cw[(c + 1) * 4];
    float4 w2 = *(const float4*)&cw[(c + 2) * 4];
    float4 w3 = *(const float4*)&cw[(c + 3) * 4];
    float4 bb = *(const float4*)&cb[c];
    float s0 = bb.x, s1 = bb.y, s2 = bb.z, s3 = bb.w;

#pragma unroll
    for (int j = 0; j < 4; j++) {
        if (l - 3 + j >= 0) {
            float4 v = *(const float4*)&xz[(size_t)(t - 3 + j) * (2 * DI) + c];
            s0 = fmaf(((const float*)&w0)[j], v.x, s0);
            s1 = fmaf(((const float*)&w1)[j], v.y, s1);
            s2 = fmaf(((const float*)&w2)[j], v.z, s2);
            s3 = fmaf(((const float*)&w3)[j], v.w, s3);
        }
    }
    float4 o;
    o.x = s0 * (1.f / (1.f + __expf(-s0)));
    o.y = s1 * (1.f / (1.f + __expf(-s1)));
    o.z = s2 * (1.f / (1.f + __expf(-s2)));
    o.w = s3 * (1.f / (1.f + __expf(-s3)));
    *(float4*)&xc[(size_t)t * DI + c] = o;
}

// ---------------------------------------------------------------------------
// Selective scan + skip(D) + gating silu(z).
// gg (consumed ONLY by GEMM6) is stored tf32-rounded so GEMM6 needs no cvt;
// numerically identical to rounding at GEMM6's smem fill.
// ---------------------------------------------------------------------------
#define TCH 32

__global__ void __launch_bounds__(64) scan_kernel(
    const float* __restrict__ xdbl, const float* __restrict__ delta,
    const float* __restrict__ xc,   const float* __restrict__ xz,
    const float* __restrict__ A_log, const float* __restrict__ Dp,
    float* __restrict__ g)
{
    const int b   = blockIdx.y;
    const int c0  = blockIdx.x * 16;
    const int tid = threadIdx.x;
    const int ci  = tid >> 2;
    const int c   = c0 + ci;
    const int sg  = tid & 3;
    const int n0  = sg * 4;

    __shared__ float s_dt[TCH][16], s_xv[TCH][16], s_z[TCH][16];
    __shared__ float s_B[TCH][16], s_C[TCH][16];

    float Av0 = -__expf(A_log[c * DS + n0 + 0]);
    float Av1 = -__expf(A_log[c * DS + n0 + 1]);
    float Av2 = -__expf(A_log[c * DS + n0 + 2]);
    float Av3 = -__expf(A_log[c * DS + n0 + 3]);
    const float Dv = Dp[c];

    float h0 = 0.f, h1 = 0.f, h2 = 0.f, h3 = 0.f;
    const size_t rowb = (size_t)b * L_;

    for (int t0 = 0; t0 < L_; t0 += TCH) {
        __syncthreads();
#pragma unroll
        for (int p = 0; p < 2; p++) {
            int i  = tid + p * 64;
            int tt = i >> 2, q = (i & 3) * 4;
            size_t r = rowb + t0 + tt;
            *(float4*)&s_dt[tt][q] = *(const float4*)&delta[r * DI + c0 + q];
            *(float4*)&s_xv[tt][q] = *(const float4*)&xc[r * DI + c0 + q];
            *(float4*)&s_z [tt][q] = *(const float4*)&xz[r * (2 * DI) + DI + c0 + q];
        }
#pragma unroll
        for (int p = 0; p < 4; p++) {
            int i  = tid + p * 64;
            int tt = i >> 3, q = i & 7;
            float4 v = *(const float4*)&xdbl[(rowb + t0 + tt) * XD + DR + q * 4];
            if (q < 4) *(float4*)&s_B[tt][q * 4] = v;
            else       *(float4*)&s_C[tt][(q - 4) * 4] = v;
        }
        __syncthreads();

#pragma unroll 4
        for (int tt = 0; tt < TCH; tt++) {
            float dt = s_dt[tt][ci];
            float xv = s_xv[tt][ci];
            float u  = dt * xv;
            float4 Bv = *(const float4*)&s_B[tt][n0];
            float4 Cv = *(const float4*)&s_C[tt][n0];

            h0 = fmaf(__expf(dt * Av0), h0, u * Bv.x);
            h1 = fmaf(__expf(dt * Av1), h1, u * Bv.y);
            h2 = fmaf(__expf(dt * Av2), h2, u * Bv.z);
            h3 = fmaf(__expf(dt * Av3), h3, u * Bv.w);

            float p = fmaf(h0, Cv.x, fmaf(h1, Cv.y, fmaf(h2, Cv.z, h3 * Cv.w)));
            p += __shfl_xor_sync(0xffffffffu, p, 1, 4);
            p += __shfl_xor_sync(0xffffffffu, p, 2, 4);

            if (sg == 0) {
                float z = s_z[tt][ci];
                float y = p + xv * Dv;
                g[(rowb + t0 + tt) * DI + c] =
                    tf32r(y * z * (1.f / (1.f + __expf(-z))));
            }
        }
    }
}

// ---------------------------------------------------------------------------
extern "C" void kernel_launch(void* const* d_in, const int* in_sizes, int n_in,
                              void* d_out, int out_size)
{
    const float* x          = (const float*)d_in[0];
    const float* in_proj_w  = (const float*)d_in[1];
    const float* conv_w     = (const float*)d_in[2];
    const float* conv_b     = (const float*)d_in[3];
    const float* x_proj_w   = (const float*)d_in[4];
    const float* dt_proj_w  = (const float*)d_in[5];
    const float* dt_proj_b  = (const float*)d_in[6];
    const float* A_log      = (const float*)d_in[7];
    const float* Dp         = (const float*)d_in[8];
    const float* out_proj_w = (const float*)d_in[9];
    float* out = (float*)d_out;

    float *xz, *xc, *xdbl, *delta, *gg, *rx, *rw1, *rw3, *rw4, *rw6;
    cudaGetSymbolAddress((void**)&xz,    g_xz);
    cudaGetSymbolAddress((void**)&xc,    g_xc);
    cudaGetSymbolAddress((void**)&xdbl,  g_xdbl);
    cudaGetSymbolAddress((void**)&delta, g_delta);
    cudaGetSymbolAddress((void**)&gg,    g_g);
    cudaGetSymbolAddress((void**)&rx,    g_rx);
    cudaGetSymbolAddress((void**)&rw1,   g_rw1);
    cudaGetSymbolAddress((void**)&rw3,   g_rw3);
    cudaGetSymbolAddress((void**)&rw4,   g_rw4);
    cudaGetSymbolAddress((void**)&rw6,   g_rw6);

    // 0) pre-round x + weights to tf32 (hoists cvt out of GEMM mainloops)
    {
        int n;
        n = MTOK * DM / 4;    round_tf32_kernel<<<(n + 255) / 256, 256>>>(x, rx, n);
        n = 2 * DI * DM / 4;  round_tf32_kernel<<<(n + 255) / 256, 256>>>(in_proj_w, rw1, n);
        n = XD * DI / 4;      round_tf32_kernel<<<(n + 255) / 256, 256>>>(x_proj_w, rw3, n);
        n = DI * DR / 4;      round_tf32_kernel<<<(n + 255) / 256, 256>>>(dt_proj_w, rw4, n);
        n = DM * DI / 4;      round_tf32_kernel<<<(n + 255) / 256, 256>>>(out_proj_w, rw6, n);
    }

    // 1) xz = x @ in_proj_w^T   (no cvt: both pre-rounded)
    mma_gemm_nt<128, 128, 16, 2, 4, 0, 0><<<dim3(32, 32), 256>>>(
        rx, rw1, xz, MTOK, 2 * DI, DM, DM, DM, 2 * DI, nullptr);

    // 2) causal depthwise conv + SiLU -> xc (unrounded)
    conv_silu_kernel<<<(MTOK * DI / 4 + 255) / 256, 256>>>(xz, conv_w, conv_b, xc);

    // 3) x_dbl = xc @ x_proj_w^T  (CVTA rounds xc at smem fill)
    mma_gemm_nt<32, 96, 16, 2, 4, 0, 1><<<dim3(1, 128), 256>>>(
        xc, rw3, xdbl, MTOK, XD, DI, DI, DI, XD, nullptr);

    // 4) delta = softplus(x_dbl[:, :64] @ dt_proj_w^T + b)  (CVTA on xdbl)
    mma_gemm_nt<128, 128, 16, 2, 4, 1, 1><<<dim3(16, 32), 256>>>(
        xdbl, rw4, delta, MTOK, DI, DR, XD, DR, DI, dt_proj_b);

    // 5) selective scan + skip(D) + gating silu(z) -> gg (tf32-rounded)
    scan_kernel<<<dim3(DI / 16, B_), 64>>>(xdbl, delta, xc, xz, A_log, Dp, gg);

    // 6) out = gg @ out_proj_w^T  (no cvt: both pre-rounded)
    mma_gemm_nt<128, 128, 16, 2, 4, 0, 0><<<dim3(8, 32), 256>>>(
        gg, rw6, out, MTOK, DM, DI, DI, DI, DM, nullptr);
}

// round 17
// speedup vs baseline: 1.5384x; 1.5384x over previous
#include <cuda_runtime.h>
#include <math.h>
#include <stdint.h>

// Problem constants
#define B_    2
#define L_    2048
#define DM    1024
#define DI    2048
#define DS    16
#define DR    64
#define XD    96            // DR + 2*DS
#define MTOK  (B_ * L_)     // 4096 tokens

// Scratch (device globals: allocation-free)
__device__ float g_xz[(size_t)MTOK * (2 * DI)];
__device__ float g_xc[(size_t)MTOK * DI];
__device__ float g_xdbl[(size_t)MTOK * XD];
__device__ float g_delta[(size_t)MTOK * DI];
__device__ float g_g[(size_t)MTOK * DI];
// Pre-rounded (tf32) copies
__device__ float g_rx [(size_t)MTOK * DM];        // x
__device__ float g_rw1[(size_t)(2 * DI) * DM];    // in_proj_w
__device__ float g_rw3[(size_t)XD * DI];          // x_proj_w
__device__ float g_rw4[(size_t)DI * DR];          // dt_proj_w
__device__ float g_rw6[(size_t)DM * DI];          // out_proj_w

// ---------------------------------------------------------------------------
// TF32 helpers
// ---------------------------------------------------------------------------
__device__ __forceinline__ unsigned f2tf32(float f) {
    unsigned r;
    asm("cvt.rna.tf32.f32 %0, %1;" : "=r"(r) : "f"(f));
    return r;
}
__device__ __forceinline__ float tf32r(float f) {
    return __uint_as_float(f2tf32(f));
}

__device__ __forceinline__ void mma_tf32(float (&d)[4], const unsigned (&a)[4],
                                         const unsigned (&b)[2]) {
    asm volatile(
        "mma.sync.aligned.m16n8k8.row.col.f32.tf32.tf32.f32 "
        "{%0,%1,%2,%3}, {%4,%5,%6,%7}, {%8,%9}, {%0,%1,%2,%3};\n"
        : "+f"(d[0]), "+f"(d[1]), "+f"(d[2]), "+f"(d[3])
        : "r"(a[0]), "r"(a[1]), "r"(a[2]), "r"(a[3]),
          "r"(b[0]), "r"(b[1]));
}

// ---------------------------------------------------------------------------
// Pre-round: dst = round_tf32(src), float4 elementwise.
// ---------------------------------------------------------------------------
__global__ void round_tf32_kernel(const float* __restrict__ src,
                                  float* __restrict__ dst, int n4)
{
    int i = blockIdx.x * blockDim.x + threadIdx.x;
    if (i >= n4) return;
    float4 v = ((const float4*)src)[i];
    v.x = tf32r(v.x); v.y = tf32r(v.y); v.z = tf32r(v.z); v.w = tf32r(v.w);
    ((float4*)dst)[i] = v;
}

// ---------------------------------------------------------------------------
// SIMT TF32 MMA GEMM — EXACT R10-measured structure (scalar smem stores,
// double-buffered, register-staged prefetch, one sync per tile).
// B operand must be pre-rounded to tf32 in gmem. A is rounded at smem fill
// iff CVTA=1 (CVTA=0 when A is already tf32 in gmem).
// EPI=0: plain store. EPI=1: +=bias, softplus.
// ---------------------------------------------------------------------------
template <int BM, int BN, int BK, int WRM, int WRN, int EPI, int CVTA>
__global__ void __launch_bounds__(256) mma_gemm_nt(
    const float* __restrict__ A, const float* __restrict__ Bw,
    float* __restrict__ C, int M, int N, int K,
    int lda, int ldb, int ldc, const float* __restrict__ bias)
{
    constexpr int WM = BM / WRM, WN = BN / WRN;
    constexpr int MI = WM / 16, NI = WN / 8;
    constexpr int LDSZ = BK + 4;
    constexpr int K4 = BK / 4;
    constexpr int AF4 = BM * K4;
    constexpr int BF4 = BN * K4;
    constexpr int AP = (AF4 + 255) / 256;
    constexpr int BP = (BF4 + 255) / 256;

    __shared__ float As[2][BM][LDSZ];
    __shared__ float Bs[2][BN][LDSZ];

    const int tid  = threadIdx.x;
    const int lane = tid & 31;
    const int warp = tid >> 5;
    const int wm = (warp % WRM) * WM;
    const int wn = (warp / WRM) * WN;
    const int m0 = blockIdx.y * BM;
    const int n0 = blockIdx.x * BN;
    const int g  = lane >> 2;
    const int tg = lane & 3;

    float4 ar[AP], br[BP];

    auto load_ab = [&](int k0) {
#pragma unroll
        for (int p = 0; p < AP; p++) {
            int i = tid + p * 256;
            if ((AF4 % 256 == 0) || i < AF4)
                ar[p] = *(const float4*)&A[(size_t)(m0 + i / K4) * lda + k0 + (i % K4) * 4];
        }
#pragma unroll
        for (int p = 0; p < BP; p++) {
            int i = tid + p * 256;
            if ((BF4 % 256 == 0) || i < BF4)
                br[p] = *(const float4*)&Bw[(size_t)(n0 + i / K4) * ldb + k0 + (i % K4) * 4];
        }
    };
    // R10-exact store pattern: 4 scalar word stores per float4.
    auto store_ab = [&](int s) {
#pragma unroll
        for (int p = 0; p < AP; p++) {
            int i = tid + p * 256;
            if ((AF4 % 256 == 0) || i < AF4) {
                unsigned* d = (unsigned*)&As[s][i / K4][(i % K4) * 4];
                if (CVTA) {
                    d[0] = f2tf32(ar[p].x); d[1] = f2tf32(ar[p].y);
                    d[2] = f2tf32(ar[p].z); d[3] = f2tf32(ar[p].w);
                } else {
                    d[0] = __float_as_uint(ar[p].x); d[1] = __float_as_uint(ar[p].y);
                    d[2] = __float_as_uint(ar[p].z); d[3] = __float_as_uint(ar[p].w);
                }
            }
        }
#pragma unroll
        for (int p = 0; p < BP; p++) {
            int i = tid + p * 256;
            if ((BF4 % 256 == 0) || i < BF4) {
                unsigned* d = (unsigned*)&Bs[s][i / K4][(i % K4) * 4];
                d[0] = __float_as_uint(br[p].x); d[1] = __float_as_uint(br[p].y);
                d[2] = __float_as_uint(br[p].z); d[3] = __float_as_uint(br[p].w);
            }
        }
    };

    float acc[MI][NI][4];
#pragma unroll
    for (int mi = 0; mi < MI; mi++)
#pragma unroll
        for (int ni = 0; ni < NI; ni++)
#pragma unroll
            for (int j = 0; j < 4; j++) acc[mi][ni][j] = 0.f;

    load_ab(0);
    store_ab(0);
    __syncthreads();

    const int nt = K / BK;
#pragma unroll 1
    for (int t = 0; t < nt; t++) {
        const int s = t & 1;
        if (t + 1 < nt) load_ab((t + 1) * BK);

#pragma unroll
        for (int kk = 0; kk < BK; kk += 8) {
            unsigned af[MI][4], bf[NI][2];
#pragma unroll
            for (int mi = 0; mi < MI; mi++) {
                const int r = wm + mi * 16;
                af[mi][0] = __float_as_uint(As[s][r + g][kk + tg]);
                af[mi][1] = __float_as_uint(As[s][r + 8 + g][kk + tg]);
                af[mi][2] = __float_as_uint(As[s][r + g][kk + 4 + tg]);
                af[mi][3] = __float_as_uint(As[s][r + 8 + g][kk + 4 + tg]);
            }
#pragma unroll
            for (int ni = 0; ni < NI; ni++) {
                const int cn = wn + ni * 8 + g;
                bf[ni][0] = __float_as_uint(Bs[s][cn][kk + tg]);
                bf[ni][1] = __float_as_uint(Bs[s][cn][kk + 4 + tg]);
            }
#pragma unroll
            for (int mi = 0; mi < MI; mi++)
#pragma unroll
                for (int ni = 0; ni < NI; ni++)
                    mma_tf32(acc[mi][ni], af[mi], bf[ni]);
        }

        if (t + 1 < nt) store_ab(s ^ 1);
        __syncthreads();
    }

#pragma unroll
    for (int mi = 0; mi < MI; mi++) {
#pragma unroll
        for (int ni = 0; ni < NI; ni++) {
#pragma unroll
            for (int half = 0; half < 2; half++) {
                int row = m0 + wm + mi * 16 + g + half * 8;
                int col = n0 + wn + ni * 8 + tg * 2;
                float v0 = acc[mi][ni][half * 2 + 0];
                float v1 = acc[mi][ni][half * 2 + 1];
                if (EPI == 1) {
                    v0 += bias[col];
                    v1 += bias[col + 1];
                    v0 = (v0 > 20.f) ? v0 : log1pf(expf(v0));
                    v1 = (v1 > 20.f) ? v1 : log1pf(expf(v1));
                }
                *(float2*)&C[(size_t)row * ldc + col] = make_float2(v0, v1);
            }
        }
    }
}

// ---------------------------------------------------------------------------
// Causal depthwise conv1d (W=4) + bias + SiLU, vectorized over 4 channels.
// Output NOT rounded (scan consumes it raw; GEMM3 rounds via CVTA).
// ---------------------------------------------------------------------------
__global__ void conv_silu_kernel(const float* __restrict__ xz,
                                 const float* __restrict__ cw,
                                 const float* __restrict__ cb,
                                 float* __restrict__ xc)
{
    int idx = blockIdx.x * blockDim.x + threadIdx.x;
    if (idx >= MTOK * DI / 4) return;
    int c4 = idx % (DI / 4);
    int t  = idx / (DI / 4);
    int l  = t % L_;
    int c  = c4 * 4;

    float4 w0 = *(const float4*)&cw[(c + 0) * 4];
    float4 w1 = *(const float4*)&cw[(c + 1) * 4];
    float4 w2 = *(const float4*)&cw[(c + 2) * 4];
    float4 w3 = *(const float4*)&cw[(c + 3) * 4];
    float4 bb = *(const float4*)&cb[c];
    float s0 = bb.x, s1 = bb.y, s2 = bb.z, s3 = bb.w;

#pragma unroll
    for (int j = 0; j < 4; j++) {
        if (l - 3 + j >= 0) {
            float4 v = *(const float4*)&xz[(size_t)(t - 3 + j) * (2 * DI) + c];
            s0 = fmaf(((const float*)&w0)[j], v.x, s0);
            s1 = fmaf(((const float*)&w1)[j], v.y, s1);
            s2 = fmaf(((const float*)&w2)[j], v.z, s2);
            s3 = fmaf(((const float*)&w3)[j], v.w, s3);
        }
    }
    float4 o;
    o.x = s0 * (1.f / (1.f + __expf(-s0)));
    o.y = s1 * (1.f / (1.f + __expf(-s1)));
    o.z = s2 * (1.f / (1.f + __expf(-s2)));
    o.w = s3 * (1.f / (1.f + __expf(-s3)));
    *(float4*)&xc[(size_t)t * DI + c] = o;
}

// ---------------------------------------------------------------------------
// Selective scan + skip(D) + gating silu(z).
// gg (consumed ONLY by GEMM6) is stored tf32-rounded so GEMM6 needs no cvt;
// numerically identical to rounding at GEMM6's smem fill.
// ---------------------------------------------------------------------------
#define TCH 32

__global__ void __launch_bounds__(64) scan_kernel(
    const float* __restrict__ xdbl, const float* __restrict__ delta,
    const float* __restrict__ xc,   const float* __restrict__ xz,
    const float* __restrict__ A_log, const float* __restrict__ Dp,
    float* __restrict__ g)
{
    const int b   = blockIdx.y;
    const int c0  = blockIdx.x * 16;
    const int tid = threadIdx.x;
    const int ci  = tid >> 2;
    const int c   = c0 + ci;
    const int sg  = tid & 3;
    const int n0  = sg * 4;

    __shared__ float s_dt[TCH][16], s_xv[TCH][16], s_z[TCH][16];
    __shared__ float s_B[TCH][16], s_C[TCH][16];

    float Av0 = -__expf(A_log[c * DS + n0 + 0]);
    float Av1 = -__expf(A_log[c * DS + n0 + 1]);
    float Av2 = -__expf(A_log[c * DS + n0 + 2]);
    float Av3 = -__expf(A_log[c * DS + n0 + 3]);
    const float Dv = Dp[c];

    float h0 = 0.f, h1 = 0.f, h2 = 0.f, h3 = 0.f;
    const size_t rowb = (size_t)b * L_;

    for (int t0 = 0; t0 < L_; t0 += TCH) {
        __syncthreads();
#pragma unroll
        for (int p = 0; p < 2; p++) {
            int i  = tid + p * 64;
            int tt = i >> 2, q = (i & 3) * 4;
            size_t r = rowb + t0 + tt;
            *(float4*)&s_dt[tt][q] = *(const float4*)&delta[r * DI + c0 + q];
            *(float4*)&s_xv[tt][q] = *(const float4*)&xc[r * DI + c0 + q];
            *(float4*)&s_z [tt][q] = *(const float4*)&xz[r * (2 * DI) + DI + c0 + q];
        }
#pragma unroll
        for (int p = 0; p < 4; p++) {
            int i  = tid + p * 64;
            int tt = i >> 3, q = i & 7;
            float4 v = *(const float4*)&xdbl[(rowb + t0 + tt) * XD + DR + q * 4];
            if (q < 4) *(float4*)&s_B[tt][q * 4] = v;
            else       *(float4*)&s_C[tt][(q - 4) * 4] = v;
        }
        __syncthreads();

#pragma unroll 4
        for (int tt = 0; tt < TCH; tt++) {
            float dt = s_dt[tt][ci];
            float xv = s_xv[tt][ci];
            float u  = dt * xv;
            float4 Bv = *(const float4*)&s_B[tt][n0];
            float4 Cv = *(const float4*)&s_C[tt][n0];

            h0 = fmaf(__expf(dt * Av0), h0, u * Bv.x);
            h1 = fmaf(__expf(dt * Av1), h1, u * Bv.y);
            h2 = fmaf(__expf(dt * Av2), h2, u * Bv.z);
            h3 = fmaf(__expf(dt * Av3), h3, u * Bv.w);

            float p = fmaf(h0, Cv.x, fmaf(h1, Cv.y, fmaf(h2, Cv.z, h3 * Cv.w)));
            p += __shfl_xor_sync(0xffffffffu, p, 1, 4);
            p += __shfl_xor_sync(0xffffffffu, p, 2, 4);

            if (sg == 0) {
                float z = s_z[tt][ci];
                float y = p + xv * Dv;
                g[(rowb + t0 + tt) * DI + c] =
                    tf32r(y * z * (1.f / (1.f + __expf(-z))));
            }
        }
    }
}

// ---------------------------------------------------------------------------
extern "C" void kernel_launch(void* const* d_in, const int* in_sizes, int n_in,
                              void* d_out, int out_size)
{
    const float* x          = (const float*)d_in[0];
    const float* in_proj_w  = (const float*)d_in[1];
    const float* conv_w     = (const float*)d_in[2];
    const float* conv_b     = (const float*)d_in[3];
    const float* x_proj_w   = (const float*)d_in[4];
    const float* dt_proj_w  = (const float*)d_in[5];
    const float* dt_proj_b  = (const float*)d_in[6];
    const float* A_log      = (const float*)d_in[7];
    const float* Dp         = (const float*)d_in[8];
    const float* out_proj_w = (const float*)d_in[9];
    float* out = (float*)d_out;

    float *xz, *xc, *xdbl, *delta, *gg, *rx, *rw1, *rw3, *rw4, *rw6;
    cudaGetSymbolAddress((void**)&xz,    g_xz);
    cudaGetSymbolAddress((void**)&xc,    g_xc);
    cudaGetSymbolAddress((void**)&xdbl,  g_xdbl);
    cudaGetSymbolAddress((void**)&delta, g_delta);
    cudaGetSymbolAddress((void**)&gg,    g_g);
    cudaGetSymbolAddress((void**)&rx,    g_rx);
    cudaGetSymbolAddress((void**)&rw1,   g_rw1);
    cudaGetSymbolAddress((void**)&rw3,   g_rw3);
    cudaGetSymbolAddress((void**)&rw4,   g_rw4);
    cudaGetSymbolAddress((void**)&rw6,   g_rw6);

    // 0) pre-round x + weights to tf32 (hoists cvt out of GEMM mainloops)
    {
        int n;
        n = MTOK * DM / 4;    round_tf32_kernel<<<(n + 255) / 256, 256>>>(x, rx, n);
        n = 2 * DI * DM / 4;  round_tf32_kernel<<<(n + 255) / 256, 256>>>(in_proj_w, rw1, n);
        n = XD * DI / 4;      round_tf32_kernel<<<(n + 255) / 256, 256>>>(x_proj_w, rw3, n);
        n = DI * DR / 4;      round_tf32_kernel<<<(n + 255) / 256, 256>>>(dt_proj_w, rw4, n);
        n = DM * DI / 4;      round_tf32_kernel<<<(n + 255) / 256, 256>>>(out_proj_w, rw6, n);
    }

    // 1) xz = x @ in_proj_w^T   (no cvt: both pre-rounded)
    mma_gemm_nt<128, 128, 16, 2, 4, 0, 0><<<dim3(32, 32), 256>>>(
        rx, rw1, xz, MTOK, 2 * DI, DM, DM, DM, 2 * DI, nullptr);

    // 2) causal depthwise conv + SiLU -> xc (unrounded)
    conv_silu_kernel<<<(MTOK * DI / 4 + 255) / 256, 256>>>(xz, conv_w, conv_b, xc);

    // 3) x_dbl = xc @ x_proj_w^T  (R10 tiling; CVTA rounds xc at smem fill)
    mma_gemm_nt<64, 96, 16, 2, 4, 0, 1><<<dim3(1, 64), 256>>>(
        xc, rw3, xdbl, MTOK, XD, DI, DI, DI, XD, nullptr);

    // 4) delta = softplus(x_dbl[:, :64] @ dt_proj_w^T + b)  (CVTA on xdbl)
    mma_gemm_nt<128, 128, 16, 2, 4, 1, 1><<<dim3(16, 32), 256>>>(
        xdbl, rw4, delta, MTOK, DI, DR, XD, DR, DI, dt_proj_b);

    // 5) selective scan + skip(D) + gating silu(z) -> gg (tf32-rounded)
    scan_kernel<<<dim3(DI / 16, B_), 64>>>(xdbl, delta, xc, xz, A_log, Dp, gg);

    // 6) out = gg @ out_proj_w^T  (no cvt: both pre-rounded)
    mma_gemm_nt<128, 128, 16, 2, 4, 0, 0><<<dim3(8, 32), 256>>>(
        gg, rw6, out, MTOK, DM, DI, DI, DI, DM, nullptr);
}